// round 5
// baseline (speedup 1.0000x reference)
#include <cuda_runtime.h>
#include <cuda.h>
#include <cstdint>

// ============================================================================
// Int8 LLaMA MLP (W8A8): dtype-robust build, v2 (reduced static footprint).
// Rounds 3/4 died to container-level failures before compile (as did the
// round-0 stub). Kernel code is byte-identical to round 3; the only change
// is static-scratch reuse: X8/Wg8/Wu8 share a pool with Wd8, which is packed
// AFTER kernel 1 (X/Wg/Wu dead by then). 241 MB -> 152 MB static.
// Probe kernel detects int8-vs-int32 wire dtype; pack kernels materialize
// guaranteed-int8 copies; GEMMs: mma.sync m16n8k32 s8 + TMA SW128, 4-stage.
// ============================================================================

#define H_DIM   4096
#define F_DIM   11008
#define M_TOK   4096
#define STAGES  4

#define K1_CHUNKS 32           // H / 128
#define K2_CHUNKS 86           // F / 128

#define K1_STAGE_BYTES (16384 + 8192 + 8192)   // A | Bg | Bu
#define K2_STAGE_BYTES (16384 + 8192)          // A | B
#define K1_SMEM (1024 + STAGES * K1_STAGE_BYTES + 1024)
#define K2_SMEM (1024 + STAGES * K2_STAGE_BYTES + 1024)

// Pool layout (lifetimes):
//   phase 1 (kernel 1): X8 @ [0,16M), Wg8 @ [16M, 16M+45M), Wu8 @ [+45M)
//   phase 2 (kernel 2): Wd8 @ [0, 45M)   (overlaps dead X8/Wg8)
#define POOL_X_OFF   0
#define POOL_WG_OFF  16777216
#define POOL_WU_OFF  61865984
#define POOL_WD_OFF  0
#define POOL_BYTES   106954752

__device__ __align__(1024) int8_t g_pool[POOL_BYTES];
__device__ __align__(1024) int8_t g_prod8[45088768];  // [M, F] intermediate
__device__ __align__(128)  int8_t g_bg8[11008];
__device__ __align__(128)  int8_t g_bu8[11008];
__device__ int g_i32mode;

// ---------------------------------------------------------------------------
// dtype probe + pack
// ---------------------------------------------------------------------------
__global__ void probe_kernel(const void* wg_raw) {
    if (threadIdx.x == 0 && blockIdx.x == 0) {
        const int* p = (const int*)wg_raw;
        int ok = 1;
        #pragma unroll 8
        for (int i = 0; i < 256; i++) {
            int v = p[i];
            if (v < -128 || v > 127) ok = 0;
        }
        g_i32mode = ok;
    }
}

// 16 output bytes per thread. i32 mode: narrow int32->int8; else raw copy.
__global__ void pack_kernel(int8_t* __restrict__ dst,
                            const void* __restrict__ src, int n16) {
    int i = blockIdx.x * blockDim.x + threadIdx.x;
    if (i >= n16) return;
    if (g_i32mode) {
        const int4* s = (const int4*)src + (size_t)i * 4;
        int out[4];
        #pragma unroll
        for (int j = 0; j < 4; j++) {
            int4 v = s[j];
            out[j] = (v.x & 0xFF) | ((v.y & 0xFF) << 8) |
                     ((v.z & 0xFF) << 16) | ((v.w & 0xFF) << 24);
        }
        ((int4*)dst)[i] = make_int4(out[0], out[1], out[2], out[3]);
    } else {
        ((int4*)dst)[i] = ((const int4*)src)[i];
    }
}

// ---------------------------------------------------------------------------
// PTX helpers
// ---------------------------------------------------------------------------
__device__ __forceinline__ uint32_t smem_u32(const void* p) {
    uint32_t a;
    asm("{ .reg .u64 t; cvta.to.shared.u64 t, %1; cvt.u32.u64 %0, t; }"
        : "=r"(a) : "l"(p));
    return a;
}

#define MBARRIER_INIT(addr, cnt) \
    asm volatile("mbarrier.init.shared.b64 [%0], %1;" \
        :: "r"((uint32_t)(addr)), "r"((uint32_t)(cnt)) : "memory")

#define MBARRIER_EXPECT_TX(addr, bytes) \
    asm volatile("mbarrier.arrive.expect_tx.shared.b64 _, [%0], %1;" \
        :: "r"((uint32_t)(addr)), "r"((uint32_t)(bytes)) : "memory")

#define MBARRIER_WAIT_PARITY(addr, parity) do {                               \
    uint32_t _mbar = (uint32_t)(addr);                                        \
    uint32_t _par  = (uint32_t)(parity);                                      \
    uint32_t _done;                                                           \
    asm volatile(                                                             \
        "{\n\t.reg .pred p;\n\t"                                              \
        "mbarrier.try_wait.parity.acquire.cta.shared::cta.b64 p, [%1], %2;\n\t" \
        "selp.b32 %0, 1, 0, p;\n\t}"                                          \
        : "=r"(_done) : "r"(_mbar), "r"(_par) : "memory");                    \
    if (!_done) {                                                             \
        asm volatile(                                                         \
            "{\n\t.reg .pred P1;\n\t"                                         \
            "WAIT_LOOP_%=:\n\t"                                               \
            "mbarrier.try_wait.parity.acquire.cta.shared::cta.b64 P1, [%0], %1, 0x989680;\n\t" \
            "@P1 bra.uni WAIT_DONE_%=;\n\t"                                   \
            "bra.uni WAIT_LOOP_%=;\n\t"                                       \
            "WAIT_DONE_%=:\n\t}"                                              \
            :: "r"(_mbar), "r"(_par) : "memory");                             \
    }                                                                         \
} while (0)

#define TMA_LOAD_2D(smem_addr, tmap, cx, cy, mbar)                            \
    asm volatile(                                                             \
        "cp.async.bulk.tensor.2d.shared::cta.global.tile.mbarrier::complete_tx::bytes " \
        "[%0], [%1, {%2, %3}], [%4];"                                         \
        :: "r"((uint32_t)(smem_addr)), "l"(tmap),                             \
           "r"((int)(cx)), "r"((int)(cy)), "r"((uint32_t)(mbar)) : "memory")

#define FENCE_PROXY_ASYNC() asm volatile("fence.proxy.async.shared::cta;" ::: "memory")

__device__ __forceinline__ uint32_t swz(uint32_t off) {
    return off ^ ((off >> 3) & 0x70);
}

__device__ __forceinline__ void ldm4(uint32_t* r, uint32_t addr) {
    asm volatile("ldmatrix.sync.aligned.m8n8.x4.shared.b16 {%0,%1,%2,%3}, [%4];"
                 : "=r"(r[0]), "=r"(r[1]), "=r"(r[2]), "=r"(r[3]) : "r"(addr));
}

__device__ __forceinline__ void mma_s8(int* c, const uint32_t* a,
                                       uint32_t b0, uint32_t b1) {
    asm volatile(
        "mma.sync.aligned.m16n8k32.row.col.s32.s8.s8.s32 "
        "{%0,%1,%2,%3}, {%4,%5,%6,%7}, {%8,%9}, {%0,%1,%2,%3};"
        : "+r"(c[0]), "+r"(c[1]), "+r"(c[2]), "+r"(c[3])
        : "r"(a[0]), "r"(a[1]), "r"(a[2]), "r"(a[3]), "r"(b0), "r"(b1));
}

// ---------------------------------------------------------------------------
// Kernel 1: fused gate + up. CTA: M=128 x F=64. 256 threads, warps 4(M)x2(N).
// ---------------------------------------------------------------------------
__global__ void __launch_bounds__(256, 1)
mlp_gateup_kernel(const __grid_constant__ CUtensorMap tmX,
                  const __grid_constant__ CUtensorMap tmWg,
                  const __grid_constant__ CUtensorMap tmWu,
                  const int8_t* __restrict__ bg,
                  const int8_t* __restrict__ bu,
                  const float* __restrict__ sc_ag,
                  const float* __restrict__ sc_bg,
                  const float* __restrict__ sc_au,
                  const float* __restrict__ sc_bu)
{
    extern __shared__ char smem_raw[];
    const uint32_t sb0  = smem_u32(smem_raw);
    const uint32_t base = (sb0 + 1023u) & ~1023u;

    const int tid  = threadIdx.x;
    const int wid  = tid >> 5;
    const int lane = tid & 31;
    const int wm   = wid & 3;
    const int wn   = wid >> 2;

    const uint32_t mb_full = base;
    const uint32_t tiles   = base + 1024;

    const int m0 = blockIdx.x * 128;
    const int f0 = blockIdx.y * 64;

    if (tid == 0) {
        #pragma unroll
        for (int s = 0; s < STAGES; s++) MBARRIER_INIT(mb_full + s * 8, 1);
        FENCE_PROXY_ASYNC();
    }
    __syncthreads();

    if (tid == 0) {
        #pragma unroll
        for (int p = 0; p < STAGES - 1; p++) {
            uint32_t st = tiles + p * K1_STAGE_BYTES;
            MBARRIER_EXPECT_TX(mb_full + p * 8, K1_STAGE_BYTES);
            TMA_LOAD_2D(st,          &tmX,  p * 128, m0, mb_full + p * 8);
            TMA_LOAD_2D(st + 16384,  &tmWg, p * 128, f0, mb_full + p * 8);
            TMA_LOAD_2D(st + 24576,  &tmWu, p * 128, f0, mb_full + p * 8);
        }
    }

    const int lr  = lane & 7;
    const int seg = lane >> 3;
    const int rowA_off = wm * 32 + lr + ((seg & 1) << 3);
    const int colA_off = (seg >> 1) << 4;
    const int rowB_off = wn * 32 + lr + ((seg >> 1) << 3);
    const int colB_off = (seg & 1) << 4;

    int cg[32], cu[32];
    #pragma unroll
    for (int i = 0; i < 32; i++) { cg[i] = 0; cu[i] = 0; }

    for (int i = 0; i < K1_CHUNKS; i++) {
        const int s  = i & (STAGES - 1);
        const int ph = (i / STAGES) & 1;
        MBARRIER_WAIT_PARITY(mb_full + s * 8, ph);

        const uint32_t abase = tiles + s * K1_STAGE_BYTES;
        const uint32_t gbase = abase + 16384;
        const uint32_t ubase = abase + 24576;

        #pragma unroll
        for (int ks = 0; ks < 4; ks++) {
            const int ca = ks * 32 + colA_off;
            const int cb = ks * 32 + colB_off;
            uint32_t a[2][4], bgr[8], bur[8];
            #pragma unroll
            for (int mb = 0; mb < 2; mb++)
                ldm4(a[mb], abase + swz((rowA_off + mb * 16) * 128 + ca));
            #pragma unroll
            for (int np = 0; np < 2; np++) {
                ldm4(bgr + np * 4, gbase + swz((rowB_off + np * 16) * 128 + cb));
                ldm4(bur + np * 4, ubase + swz((rowB_off + np * 16) * 128 + cb));
            }
            #pragma unroll
            for (int mb = 0; mb < 2; mb++)
                #pragma unroll
                for (int nb = 0; nb < 4; nb++) {
                    mma_s8(cg + (mb * 4 + nb) * 4, a[mb], bgr[nb * 2], bgr[nb * 2 + 1]);
                    mma_s8(cu + (mb * 4 + nb) * 4, a[mb], bur[nb * 2], bur[nb * 2 + 1]);
                }
        }

        __syncthreads();
        const int nx = i + STAGES - 1;
        if (tid == 0 && nx < K1_CHUNKS) {
            const int s2 = nx & (STAGES - 1);
            uint32_t st = tiles + s2 * K1_STAGE_BYTES;
            MBARRIER_EXPECT_TX(mb_full + s2 * 8, K1_STAGE_BYTES);
            TMA_LOAD_2D(st,          &tmX,  nx * 128, m0, mb_full + s2 * 8);
            TMA_LOAD_2D(st + 16384,  &tmWg, nx * 128, f0, mb_full + s2 * 8);
            TMA_LOAD_2D(st + 24576,  &tmWu, nx * 128, f0, mb_full + s2 * 8);
        }
    }

    const float ag  = *sc_ag;
    const float bgs = *sc_bg;
    const float au  = *sc_au;
    const float bus = *sc_bu;
    const int g   = lane >> 2;
    const int tig = lane & 3;

    #pragma unroll
    for (int mb = 0; mb < 2; mb++) {
        #pragma unroll
        for (int nb = 0; nb < 4; nb++) {
            const int idx = (mb * 4 + nb) * 4;
            const int r0  = m0 + wm * 32 + mb * 16 + g;
            const int col = f0 + wn * 32 + nb * 8 + 2 * tig;
            const float b0f = (float)bg[col];
            const float b1f = (float)bg[col + 1];
            const float u0f = (float)bu[col];
            const float u1f = (float)bu[col + 1];
            #pragma unroll
            for (int half = 0; half < 2; half++) {
                const int row = r0 + half * 8;
                const int c0  = idx + half * 2;
                float gx0 = __fadd_rn(__fmul_rn(ag, (float)cg[c0]),     __fmul_rn(bgs, b0f));
                float gx1 = __fadd_rn(__fmul_rn(ag, (float)cg[c0 + 1]), __fmul_rn(bgs, b1f));
                gx0 = fminf(rintf(fmaxf(gx0, 0.0f)), 127.0f);
                gx1 = fminf(rintf(fmaxf(gx1, 0.0f)), 127.0f);
                float ux0 = __fadd_rn(__fmul_rn(au, (float)cu[c0]),     __fmul_rn(bus, u0f));
                float ux1 = __fadd_rn(__fmul_rn(au, (float)cu[c0 + 1]), __fmul_rn(bus, u1f));
                ux0 = fminf(fmaxf(rintf(ux0), -128.0f), 127.0f);
                ux1 = fminf(fmaxf(rintf(ux1), -128.0f), 127.0f);
                const int p0 = (int)gx0 * (int)ux0;
                const int p1 = (int)gx1 * (int)ux1;
                const uint16_t pk = (uint16_t)(((p1 & 0xFF) << 8) | (p0 & 0xFF));
                *(uint16_t*)(g_prod8 + (size_t)row * F_DIM + col) = pk;
            }
        }
    }
}

// ---------------------------------------------------------------------------
// Kernel 2: down GEMM. CTA: M=128 x H=64. 256 threads, warps 4x2.
// ---------------------------------------------------------------------------
__global__ void __launch_bounds__(256, 1)
mlp_down_kernel(const __grid_constant__ CUtensorMap tmP,
                const __grid_constant__ CUtensorMap tmWd,
                const float* __restrict__ sc_ad,
                const float* __restrict__ bias_d,
                float* __restrict__ out)
{
    extern __shared__ char smem_raw[];
    const uint32_t sb0  = smem_u32(smem_raw);
    const uint32_t base = (sb0 + 1023u) & ~1023u;

    const int tid  = threadIdx.x;
    const int wid  = tid >> 5;
    const int lane = tid & 31;
    const int wm   = wid & 3;
    const int wn   = wid >> 2;

    const uint32_t mb_full = base;
    const uint32_t tiles   = base + 1024;

    const int m0 = blockIdx.x * 128;
    const int h0 = blockIdx.y * 64;

    if (tid == 0) {
        #pragma unroll
        for (int s = 0; s < STAGES; s++) MBARRIER_INIT(mb_full + s * 8, 1);
        FENCE_PROXY_ASYNC();
    }
    __syncthreads();

    if (tid == 0) {
        #pragma unroll
        for (int p = 0; p < STAGES - 1; p++) {
            uint32_t st = tiles + p * K2_STAGE_BYTES;
            MBARRIER_EXPECT_TX(mb_full + p * 8, K2_STAGE_BYTES);
            TMA_LOAD_2D(st,         &tmP,  p * 128, m0, mb_full + p * 8);
            TMA_LOAD_2D(st + 16384, &tmWd, p * 128, h0, mb_full + p * 8);
        }
    }

    const int lr  = lane & 7;
    const int seg = lane >> 3;
    const int rowA_off = wm * 32 + lr + ((seg & 1) << 3);
    const int colA_off = (seg >> 1) << 4;
    const int rowB_off = wn * 32 + lr + ((seg >> 1) << 3);
    const int colB_off = (seg & 1) << 4;

    int cd[32];
    #pragma unroll
    for (int i = 0; i < 32; i++) cd[i] = 0;

    for (int i = 0; i < K2_CHUNKS; i++) {
        const int s  = i & (STAGES - 1);
        const int ph = (i / STAGES) & 1;
        MBARRIER_WAIT_PARITY(mb_full + s * 8, ph);

        const uint32_t abase = tiles + s * K2_STAGE_BYTES;
        const uint32_t bbase = abase + 16384;

        #pragma unroll
        for (int ks = 0; ks < 4; ks++) {
            const int ca = ks * 32 + colA_off;
            const int cb = ks * 32 + colB_off;
            uint32_t a[2][4], br[8];
            #pragma unroll
            for (int mb = 0; mb < 2; mb++)
                ldm4(a[mb], abase + swz((rowA_off + mb * 16) * 128 + ca));
            #pragma unroll
            for (int np = 0; np < 2; np++)
                ldm4(br + np * 4, bbase + swz((rowB_off + np * 16) * 128 + cb));
            #pragma unroll
            for (int mb = 0; mb < 2; mb++)
                #pragma unroll
                for (int nb = 0; nb < 4; nb++)
                    mma_s8(cd + (mb * 4 + nb) * 4, a[mb], br[nb * 2], br[nb * 2 + 1]);
        }

        __syncthreads();
        const int nx = i + STAGES - 1;
        if (tid == 0 && nx < K2_CHUNKS) {
            const int s2 = nx & (STAGES - 1);
            uint32_t st = tiles + s2 * K2_STAGE_BYTES;
            MBARRIER_EXPECT_TX(mb_full + s2 * 8, K2_STAGE_BYTES);
            TMA_LOAD_2D(st,         &tmP,  nx * 128, m0, mb_full + s2 * 8);
            TMA_LOAD_2D(st + 16384, &tmWd, nx * 128, h0, mb_full + s2 * 8);
        }
    }

    const float ad = *sc_ad;
    const int g   = lane >> 2;
    const int tig = lane & 3;

    #pragma unroll
    for (int mb = 0; mb < 2; mb++) {
        #pragma unroll
        for (int nb = 0; nb < 4; nb++) {
            const int idx = (mb * 4 + nb) * 4;
            const int r0  = m0 + wm * 32 + mb * 16 + g;
            const int col = h0 + wn * 32 + nb * 8 + 2 * tig;
            const float bb0 = bias_d[col];
            const float bb1 = bias_d[col + 1];
            #pragma unroll
            for (int half = 0; half < 2; half++) {
                const int row = r0 + half * 8;
                const int c0  = idx + half * 2;
                float2 v;
                v.x = __fadd_rn(__fmul_rn(ad, (float)cd[c0]),     bb0);
                v.y = __fadd_rn(__fmul_rn(ad, (float)cd[c0 + 1]), bb1);
                *(float2*)(out + (size_t)row * H_DIM + col) = v;
            }
        }
    }
}

// ---------------------------------------------------------------------------
// Host side
// ---------------------------------------------------------------------------
typedef CUresult (CUDAAPI *PFN_encodeTiled)(
    CUtensorMap*, CUtensorMapDataType, cuuint32_t, void*,
    const cuuint64_t*, const cuuint64_t*, const cuuint32_t*, const cuuint32_t*,
    CUtensorMapInterleave, CUtensorMapSwizzle, CUtensorMapL2promotion,
    CUtensorMapFloatOOBfill);

static PFN_encodeTiled get_encoder() {
    void* fn = nullptr;
    cudaDriverEntryPointQueryResult qr;
#if CUDART_VERSION >= 12050
    cudaGetDriverEntryPointByVersion("cuTensorMapEncodeTiled", &fn, 12000,
                                     cudaEnableDefault, &qr);
#else
    cudaGetDriverEntryPoint("cuTensorMapEncodeTiled", &fn, cudaEnableDefault, &qr);
#endif
    return (PFN_encodeTiled)fn;
}

static void make2d(PFN_encodeTiled enc, CUtensorMap* tm, void* ptr,
                   uint64_t d0, uint64_t d1, uint64_t stride0_bytes,
                   uint32_t b0, uint32_t b1) {
    cuuint64_t dims[2]    = {d0, d1};
    cuuint64_t strides[1] = {stride0_bytes};
    cuuint32_t box[2]     = {b0, b1};
    cuuint32_t es[2]      = {1, 1};
    enc(tm, CU_TENSOR_MAP_DATA_TYPE_UINT8, 2, ptr, dims, strides, box, es,
        CU_TENSOR_MAP_INTERLEAVE_NONE, CU_TENSOR_MAP_SWIZZLE_128B,
        CU_TENSOR_MAP_L2_PROMOTION_L2_128B, CU_TENSOR_MAP_FLOAT_OOB_FILL_NONE);
}

extern "C" void kernel_launch(void* const* d_in, const int* in_sizes, int n_in,
                              void* d_out, int out_size) {
    (void)in_sizes; (void)n_in; (void)out_size;

    const void*  X_raw  = d_in[0];
    const void*  Wg_raw = d_in[1];
    const void*  bg_raw = d_in[2];
    const void*  Wu_raw = d_in[3];
    const void*  bu_raw = d_in[4];
    const void*  Wd_raw = d_in[5];
    const float* ag  = (const float*)d_in[6];
    const float* bgs = (const float*)d_in[7];
    const float* au  = (const float*)d_in[8];
    const float* bus = (const float*)d_in[9];
    const float* ad  = (const float*)d_in[10];
    const float* bd  = (const float*)d_in[11];
    float* out = (float*)d_out;

    void *ppool = nullptr, *pbg = nullptr, *pbu = nullptr, *pprod = nullptr;
    cudaGetSymbolAddress(&ppool, g_pool);
    cudaGetSymbolAddress(&pbg,   g_bg8);
    cudaGetSymbolAddress(&pbu,   g_bu8);
    cudaGetSymbolAddress(&pprod, g_prod8);

    PFN_encodeTiled enc = get_encoder();
    if (!enc || !ppool || !pprod) return;

    int8_t* pX  = (int8_t*)ppool + POOL_X_OFF;
    int8_t* pWg = (int8_t*)ppool + POOL_WG_OFF;
    int8_t* pWu = (int8_t*)ppool + POOL_WU_OFF;
    int8_t* pWd = (int8_t*)ppool + POOL_WD_OFF;   // reused after kernel 1

    // 1) probe wire dtype (int8 vs int32-promoted)
    probe_kernel<<<1, 32>>>(Wg_raw);

    // 2) pack phase-1 operands
    const int nX  = M_TOK * H_DIM / 16;      // 1048576
    const int nW  = F_DIM * H_DIM / 16;      // 2818048
    const int nB  = F_DIM / 16;              // 688
    pack_kernel<<<(nX + 255) / 256, 256>>>(pX,  X_raw,  nX);
    pack_kernel<<<(nW + 255) / 256, 256>>>(pWg, Wg_raw, nW);
    pack_kernel<<<(nW + 255) / 256, 256>>>(pWu, Wu_raw, nW);
    pack_kernel<<<(nB + 255) / 256, 256>>>((int8_t*)pbg, bg_raw, nB);
    pack_kernel<<<(nB + 255) / 256, 256>>>((int8_t*)pbu, bu_raw, nB);

    // 3) descriptors
    CUtensorMap tmX, tmWg, tmWu, tmP, tmWd;
    make2d(enc, &tmX,  pX,    H_DIM, M_TOK, H_DIM, 128, 128);
    make2d(enc, &tmWg, pWg,   H_DIM, F_DIM, H_DIM, 128, 64);
    make2d(enc, &tmWu, pWu,   H_DIM, F_DIM, H_DIM, 128, 64);
    make2d(enc, &tmP,  pprod, F_DIM, M_TOK, F_DIM, 128, 128);
    make2d(enc, &tmWd, pWd,   F_DIM, H_DIM, F_DIM, 128, 64);

    cudaFuncSetAttribute(mlp_gateup_kernel,
                         cudaFuncAttributeMaxDynamicSharedMemorySize, K1_SMEM);
    cudaFuncSetAttribute(mlp_down_kernel,
                         cudaFuncAttributeMaxDynamicSharedMemorySize, K2_SMEM);

    // 4) kernel 1 (consumes X/Wg/Wu from pool)
    dim3 g1(M_TOK / 128, F_DIM / 64);   // (32, 172)
    mlp_gateup_kernel<<<g1, 256, K1_SMEM>>>(tmX, tmWg, tmWu,
                                            (const int8_t*)pbg, (const int8_t*)pbu,
                                            ag, bgs, au, bus);

    // 5) pack Wd into the pool (X/Wg now dead; stream order guarantees safety)
    pack_kernel<<<(nW + 255) / 256, 256>>>(pWd, Wd_raw, nW);

    // 6) kernel 2
    dim3 g2(M_TOK / 128, H_DIM / 64);   // (32, 64)
    mlp_down_kernel<<<g2, 256, K2_SMEM>>>(tmP, tmWd, ad, bd, out);
}

// round 6
// speedup vs baseline: 1.0595x; 1.0595x over previous
#include <cuda_runtime.h>
#include <cuda.h>
#include <cstdint>

// ============================================================================
// Int8 LLaMA MLP (W8A8), round 6: fat warp tiles to kill smem-bandwidth bound.
//   K1: CTA 128x128, 8 warps 2(M)x4(N), warp 64x32, dual accум (gate+up)
//   K2: CTA 256x128, 8 warps 4(M)x2(N), warp 64x64
// Packs (int32-wire -> int8) unchanged (measured 77% of HBM peak).
// mma.sync m16n8k32 s8 + TMA SW128 + mbarrier, 4 stages, TMA issued at top.
// ============================================================================

#define H_DIM   4096
#define F_DIM   11008
#define M_TOK   4096
#define STAGES  4

#define K1_CHUNKS 32           // H / 128
#define K2_CHUNKS 86           // F / 128

#define K1_STAGE_BYTES (16384 + 16384 + 16384)   // A(128x128) | Bg(128x128) | Bu
#define K2_STAGE_BYTES (32768 + 16384)           // A(256x128) | B(128x128)
#define K1_SMEM (1024 + STAGES * K1_STAGE_BYTES + 1024)   // 198656
#define K2_SMEM (1024 + STAGES * K2_STAGE_BYTES + 1024)   // 198656

// Pool layout (lifetimes):
//   phase 1 (kernel 1): X8 @ [0,16M), Wg8 @ [16M,+45M), Wu8 @ [+45M)
//   phase 2 (kernel 2): Wd8 @ [0, 45M)   (overlaps dead X8/Wg8)
#define POOL_X_OFF   0
#define POOL_WG_OFF  16777216
#define POOL_WU_OFF  61865984
#define POOL_WD_OFF  0
#define POOL_BYTES   106954752

__device__ __align__(1024) int8_t g_pool[POOL_BYTES];
__device__ __align__(1024) int8_t g_prod8[45088768];  // [M, F] intermediate
__device__ __align__(128)  int8_t g_bg8[11008];
__device__ __align__(128)  int8_t g_bu8[11008];
__device__ int g_i32mode;

// ---------------------------------------------------------------------------
// dtype probe + pack
// ---------------------------------------------------------------------------
__global__ void probe_kernel(const void* wg_raw) {
    if (threadIdx.x == 0 && blockIdx.x == 0) {
        const int* p = (const int*)wg_raw;
        int ok = 1;
        #pragma unroll 8
        for (int i = 0; i < 256; i++) {
            int v = p[i];
            if (v < -128 || v > 127) ok = 0;
        }
        g_i32mode = ok;
    }
}

__global__ void pack_kernel(int8_t* __restrict__ dst,
                            const void* __restrict__ src, int n16) {
    int i = blockIdx.x * blockDim.x + threadIdx.x;
    if (i >= n16) return;
    if (g_i32mode) {
        const int4* s = (const int4*)src + (size_t)i * 4;
        int out[4];
        #pragma unroll
        for (int j = 0; j < 4; j++) {
            int4 v = s[j];
            out[j] = (v.x & 0xFF) | ((v.y & 0xFF) << 8) |
                     ((v.z & 0xFF) << 16) | ((v.w & 0xFF) << 24);
        }
        ((int4*)dst)[i] = make_int4(out[0], out[1], out[2], out[3]);
    } else {
        ((int4*)dst)[i] = ((const int4*)src)[i];
    }
}

// ---------------------------------------------------------------------------
// PTX helpers
// ---------------------------------------------------------------------------
__device__ __forceinline__ uint32_t smem_u32(const void* p) {
    uint32_t a;
    asm("{ .reg .u64 t; cvta.to.shared.u64 t, %1; cvt.u32.u64 %0, t; }"
        : "=r"(a) : "l"(p));
    return a;
}

#define MBARRIER_INIT(addr, cnt) \
    asm volatile("mbarrier.init.shared.b64 [%0], %1;" \
        :: "r"((uint32_t)(addr)), "r"((uint32_t)(cnt)) : "memory")

#define MBARRIER_EXPECT_TX(addr, bytes) \
    asm volatile("mbarrier.arrive.expect_tx.shared.b64 _, [%0], %1;" \
        :: "r"((uint32_t)(addr)), "r"((uint32_t)(bytes)) : "memory")

#define MBARRIER_WAIT_PARITY(addr, parity) do {                               \
    uint32_t _mbar = (uint32_t)(addr);                                        \
    uint32_t _par  = (uint32_t)(parity);                                      \
    uint32_t _done;                                                           \
    asm volatile(                                                             \
        "{\n\t.reg .pred p;\n\t"                                              \
        "mbarrier.try_wait.parity.acquire.cta.shared::cta.b64 p, [%1], %2;\n\t" \
        "selp.b32 %0, 1, 0, p;\n\t}"                                          \
        : "=r"(_done) : "r"(_mbar), "r"(_par) : "memory");                    \
    if (!_done) {                                                             \
        asm volatile(                                                         \
            "{\n\t.reg .pred P1;\n\t"                                         \
            "WAIT_LOOP_%=:\n\t"                                               \
            "mbarrier.try_wait.parity.acquire.cta.shared::cta.b64 P1, [%0], %1, 0x989680;\n\t" \
            "@P1 bra.uni WAIT_DONE_%=;\n\t"                                   \
            "bra.uni WAIT_LOOP_%=;\n\t"                                       \
            "WAIT_DONE_%=:\n\t}"                                              \
            :: "r"(_mbar), "r"(_par) : "memory");                             \
    }                                                                         \
} while (0)

#define TMA_LOAD_2D(smem_addr, tmap, cx, cy, mbar)                            \
    asm volatile(                                                             \
        "cp.async.bulk.tensor.2d.shared::cta.global.tile.mbarrier::complete_tx::bytes " \
        "[%0], [%1, {%2, %3}], [%4];"                                         \
        :: "r"((uint32_t)(smem_addr)), "l"(tmap),                             \
           "r"((int)(cx)), "r"((int)(cy)), "r"((uint32_t)(mbar)) : "memory")

#define FENCE_PROXY_ASYNC() asm volatile("fence.proxy.async.shared::cta;" ::: "memory")

__device__ __forceinline__ uint32_t swz(uint32_t off) {
    return off ^ ((off >> 3) & 0x70);
}

__device__ __forceinline__ void ldm4(uint32_t* r, uint32_t addr) {
    asm volatile("ldmatrix.sync.aligned.m8n8.x4.shared.b16 {%0,%1,%2,%3}, [%4];"
                 : "=r"(r[0]), "=r"(r[1]), "=r"(r[2]), "=r"(r[3]) : "r"(addr));
}

__device__ __forceinline__ void mma_s8(int* c, const uint32_t* a,
                                       uint32_t b0, uint32_t b1) {
    asm volatile(
        "mma.sync.aligned.m16n8k32.row.col.s32.s8.s8.s32 "
        "{%0,%1,%2,%3}, {%4,%5,%6,%7}, {%8,%9}, {%0,%1,%2,%3};"
        : "+r"(c[0]), "+r"(c[1]), "+r"(c[2]), "+r"(c[3])
        : "r"(a[0]), "r"(a[1]), "r"(a[2]), "r"(a[3]), "r"(b0), "r"(b1));
}

// ---------------------------------------------------------------------------
// Kernel 1: fused gate + up. CTA 128(M)x128(F). 8 warps 2(M)x4(N), warp 64x32.
// ---------------------------------------------------------------------------
__global__ void __launch_bounds__(256, 1)
mlp_gateup_kernel(const __grid_constant__ CUtensorMap tmX,
                  const __grid_constant__ CUtensorMap tmWg,
                  const __grid_constant__ CUtensorMap tmWu,
                  const int8_t* __restrict__ bg,
                  const int8_t* __restrict__ bu,
                  const float* __restrict__ sc_ag,
                  const float* __restrict__ sc_bg,
                  const float* __restrict__ sc_au,
                  const float* __restrict__ sc_bu)
{
    extern __shared__ char smem_raw[];
    const uint32_t sb0  = smem_u32(smem_raw);
    const uint32_t base = (sb0 + 1023u) & ~1023u;

    const int tid  = threadIdx.x;
    const int wid  = tid >> 5;
    const int lane = tid & 31;
    const int wm   = wid & 1;     // M warp coord (0..1), rows wm*64
    const int wn   = wid >> 1;    // N warp coord (0..3), cols wn*32

    const uint32_t mb_full = base;
    const uint32_t tiles   = base + 1024;

    const int m0 = blockIdx.x * 128;
    const int f0 = blockIdx.y * 128;

    if (tid == 0) {
        #pragma unroll
        for (int s = 0; s < STAGES; s++) MBARRIER_INIT(mb_full + s * 8, 1);
        FENCE_PROXY_ASYNC();
    }
    __syncthreads();

    if (tid == 0) {
        #pragma unroll
        for (int p = 0; p < STAGES - 1; p++) {
            uint32_t st = tiles + p * K1_STAGE_BYTES;
            MBARRIER_EXPECT_TX(mb_full + p * 8, K1_STAGE_BYTES);
            TMA_LOAD_2D(st,          &tmX,  p * 128, m0, mb_full + p * 8);
            TMA_LOAD_2D(st + 16384,  &tmWg, p * 128, f0, mb_full + p * 8);
            TMA_LOAD_2D(st + 32768,  &tmWu, p * 128, f0, mb_full + p * 8);
        }
    }

    const int lr  = lane & 7;
    const int seg = lane >> 3;
    const int rowA_off = wm * 64 + lr + ((seg & 1) << 3);
    const int colA_off = (seg >> 1) << 4;
    const int rowB_off = wn * 32 + lr + ((seg >> 1) << 3);
    const int colB_off = (seg & 1) << 4;

    int cg[64], cu[64];
    #pragma unroll
    for (int i = 0; i < 64; i++) { cg[i] = 0; cu[i] = 0; }

    for (int i = 0; i < K1_CHUNKS; i++) {
        const int s  = i & (STAGES - 1);
        const int ph = (i >> 2) & 1;
        MBARRIER_WAIT_PARITY(mb_full + s * 8, ph);

        // stage (i+3)&3 == (i-1)&3 was fully consumed before last __syncthreads
        const int nx = i + STAGES - 1;
        if (tid == 0 && nx < K1_CHUNKS) {
            const int s2 = nx & (STAGES - 1);
            uint32_t st = tiles + s2 * K1_STAGE_BYTES;
            MBARRIER_EXPECT_TX(mb_full + s2 * 8, K1_STAGE_BYTES);
            TMA_LOAD_2D(st,          &tmX,  nx * 128, m0, mb_full + s2 * 8);
            TMA_LOAD_2D(st + 16384,  &tmWg, nx * 128, f0, mb_full + s2 * 8);
            TMA_LOAD_2D(st + 32768,  &tmWu, nx * 128, f0, mb_full + s2 * 8);
        }

        const uint32_t abase = tiles + s * K1_STAGE_BYTES;
        const uint32_t gbase = abase + 16384;
        const uint32_t ubase = abase + 32768;

        #pragma unroll
        for (int ks = 0; ks < 4; ks++) {
            const int ca = ks * 32 + colA_off;
            const int cb = ks * 32 + colB_off;
            uint32_t a[4][4], bgr[8], bur[8];
            #pragma unroll
            for (int mb = 0; mb < 4; mb++)
                ldm4(a[mb], abase + swz((rowA_off + mb * 16) * 128 + ca));
            #pragma unroll
            for (int np = 0; np < 2; np++) {
                ldm4(bgr + np * 4, gbase + swz((rowB_off + np * 16) * 128 + cb));
                ldm4(bur + np * 4, ubase + swz((rowB_off + np * 16) * 128 + cb));
            }
            #pragma unroll
            for (int mb = 0; mb < 4; mb++)
                #pragma unroll
                for (int nb = 0; nb < 4; nb++) {
                    mma_s8(cg + (mb * 4 + nb) * 4, a[mb], bgr[nb * 2], bgr[nb * 2 + 1]);
                    mma_s8(cu + (mb * 4 + nb) * 4, a[mb], bur[nb * 2], bur[nb * 2 + 1]);
                }
        }

        __syncthreads();
    }

    // epilogue: requant g/u, wrap-multiply, store int8 pairs
    const float ag  = *sc_ag;
    const float bgs = *sc_bg;
    const float au  = *sc_au;
    const float bus = *sc_bu;
    const int g   = lane >> 2;
    const int tig = lane & 3;

    #pragma unroll
    for (int mb = 0; mb < 4; mb++) {
        #pragma unroll
        for (int nb = 0; nb < 4; nb++) {
            const int idx = (mb * 4 + nb) * 4;
            const int r0  = m0 + wm * 64 + mb * 16 + g;
            const int col = f0 + wn * 32 + nb * 8 + 2 * tig;
            const float b0f = (float)bg[col];
            const float b1f = (float)bg[col + 1];
            const float u0f = (float)bu[col];
            const float u1f = (float)bu[col + 1];
            #pragma unroll
            for (int half = 0; half < 2; half++) {
                const int row = r0 + half * 8;
                const int c0  = idx + half * 2;
                float gx0 = __fadd_rn(__fmul_rn(ag, (float)cg[c0]),     __fmul_rn(bgs, b0f));
                float gx1 = __fadd_rn(__fmul_rn(ag, (float)cg[c0 + 1]), __fmul_rn(bgs, b1f));
                gx0 = fminf(rintf(fmaxf(gx0, 0.0f)), 127.0f);
                gx1 = fminf(rintf(fmaxf(gx1, 0.0f)), 127.0f);
                float ux0 = __fadd_rn(__fmul_rn(au, (float)cu[c0]),     __fmul_rn(bus, u0f));
                float ux1 = __fadd_rn(__fmul_rn(au, (float)cu[c0 + 1]), __fmul_rn(bus, u1f));
                ux0 = fminf(fmaxf(rintf(ux0), -128.0f), 127.0f);
                ux1 = fminf(fmaxf(rintf(ux1), -128.0f), 127.0f);
                const int p0 = (int)gx0 * (int)ux0;
                const int p1 = (int)gx1 * (int)ux1;
                const uint16_t pk = (uint16_t)(((p1 & 0xFF) << 8) | (p0 & 0xFF));
                *(uint16_t*)(g_prod8 + (size_t)row * F_DIM + col) = pk;
            }
        }
    }
}

// ---------------------------------------------------------------------------
// Kernel 2: down GEMM. CTA 256(M)x128(H). 8 warps 4(M)x2(N), warp 64x64.
// ---------------------------------------------------------------------------
__global__ void __launch_bounds__(256, 1)
mlp_down_kernel(const __grid_constant__ CUtensorMap tmP,
                const __grid_constant__ CUtensorMap tmWd,
                const float* __restrict__ sc_ad,
                const float* __restrict__ bias_d,
                float* __restrict__ out)
{
    extern __shared__ char smem_raw[];
    const uint32_t sb0  = smem_u32(smem_raw);
    const uint32_t base = (sb0 + 1023u) & ~1023u;

    const int tid  = threadIdx.x;
    const int wid  = tid >> 5;
    const int lane = tid & 31;
    const int wm   = wid & 3;     // rows wm*64
    const int wn   = wid >> 2;    // cols wn*64

    const uint32_t mb_full = base;
    const uint32_t tiles   = base + 1024;

    const int m0 = blockIdx.x * 256;
    const int h0 = blockIdx.y * 128;

    if (tid == 0) {
        #pragma unroll
        for (int s = 0; s < STAGES; s++) MBARRIER_INIT(mb_full + s * 8, 1);
        FENCE_PROXY_ASYNC();
    }
    __syncthreads();

    if (tid == 0) {
        #pragma unroll
        for (int p = 0; p < STAGES - 1; p++) {
            uint32_t st = tiles + p * K2_STAGE_BYTES;
            MBARRIER_EXPECT_TX(mb_full + p * 8, K2_STAGE_BYTES);
            TMA_LOAD_2D(st,         &tmP,  p * 128, m0, mb_full + p * 8);
            TMA_LOAD_2D(st + 32768, &tmWd, p * 128, h0, mb_full + p * 8);
        }
    }

    const int lr  = lane & 7;
    const int seg = lane >> 3;
    const int rowA_off = wm * 64 + lr + ((seg & 1) << 3);
    const int colA_off = (seg >> 1) << 4;
    const int rowB_off = wn * 64 + lr + ((seg >> 1) << 3);
    const int colB_off = (seg & 1) << 4;

    int cd[128];
    #pragma unroll
    for (int i = 0; i < 128; i++) cd[i] = 0;

    for (int i = 0; i < K2_CHUNKS; i++) {
        const int s  = i & (STAGES - 1);
        const int ph = (i >> 2) & 1;
        MBARRIER_WAIT_PARITY(mb_full + s * 8, ph);

        const int nx = i + STAGES - 1;
        if (tid == 0 && nx < K2_CHUNKS) {
            const int s2 = nx & (STAGES - 1);
            uint32_t st = tiles + s2 * K2_STAGE_BYTES;
            MBARRIER_EXPECT_TX(mb_full + s2 * 8, K2_STAGE_BYTES);
            TMA_LOAD_2D(st,         &tmP,  nx * 128, m0, mb_full + s2 * 8);
            TMA_LOAD_2D(st + 32768, &tmWd, nx * 128, h0, mb_full + s2 * 8);
        }

        const uint32_t abase = tiles + s * K2_STAGE_BYTES;
        const uint32_t bbase = abase + 32768;

        #pragma unroll
        for (int ks = 0; ks < 4; ks++) {
            const int ca = ks * 32 + colA_off;
            const int cb = ks * 32 + colB_off;
            uint32_t a[4][4], br[16];
            #pragma unroll
            for (int mb = 0; mb < 4; mb++)
                ldm4(a[mb], abase + swz((rowA_off + mb * 16) * 128 + ca));
            #pragma unroll
            for (int np = 0; np < 4; np++)
                ldm4(br + np * 4, bbase + swz((rowB_off + np * 16) * 128 + cb));
            #pragma unroll
            for (int mb = 0; mb < 4; mb++)
                #pragma unroll
                for (int nb = 0; nb < 8; nb++)
                    mma_s8(cd + (mb * 8 + nb) * 4, a[mb], br[nb * 2], br[nb * 2 + 1]);
        }

        __syncthreads();
    }

    const float ad = *sc_ad;
    const int g   = lane >> 2;
    const int tig = lane & 3;

    #pragma unroll
    for (int mb = 0; mb < 4; mb++) {
        #pragma unroll
        for (int nb = 0; nb < 8; nb++) {
            const int idx = (mb * 8 + nb) * 4;
            const int r0  = m0 + wm * 64 + mb * 16 + g;
            const int col = h0 + wn * 64 + nb * 8 + 2 * tig;
            const float bb0 = bias_d[col];
            const float bb1 = bias_d[col + 1];
            #pragma unroll
            for (int half = 0; half < 2; half++) {
                const int row = r0 + half * 8;
                const int c0  = idx + half * 2;
                float2 v;
                v.x = __fadd_rn(__fmul_rn(ad, (float)cd[c0]),     bb0);
                v.y = __fadd_rn(__fmul_rn(ad, (float)cd[c0 + 1]), bb1);
                *(float2*)(out + (size_t)row * H_DIM + col) = v;
            }
        }
    }
}

// ---------------------------------------------------------------------------
// Host side
// ---------------------------------------------------------------------------
typedef CUresult (CUDAAPI *PFN_encodeTiled)(
    CUtensorMap*, CUtensorMapDataType, cuuint32_t, void*,
    const cuuint64_t*, const cuuint64_t*, const cuuint32_t*, const cuuint32_t*,
    CUtensorMapInterleave, CUtensorMapSwizzle, CUtensorMapL2promotion,
    CUtensorMapFloatOOBfill);

static PFN_encodeTiled get_encoder() {
    void* fn = nullptr;
    cudaDriverEntryPointQueryResult qr;
#if CUDART_VERSION >= 12050
    cudaGetDriverEntryPointByVersion("cuTensorMapEncodeTiled", &fn, 12000,
                                     cudaEnableDefault, &qr);
#else
    cudaGetDriverEntryPoint("cuTensorMapEncodeTiled", &fn, cudaEnableDefault, &qr);
#endif
    return (PFN_encodeTiled)fn;
}

static void make2d(PFN_encodeTiled enc, CUtensorMap* tm, void* ptr,
                   uint64_t d0, uint64_t d1, uint64_t stride0_bytes,
                   uint32_t b0, uint32_t b1) {
    cuuint64_t dims[2]    = {d0, d1};
    cuuint64_t strides[1] = {stride0_bytes};
    cuuint32_t box[2]     = {b0, b1};
    cuuint32_t es[2]      = {1, 1};
    enc(tm, CU_TENSOR_MAP_DATA_TYPE_UINT8, 2, ptr, dims, strides, box, es,
        CU_TENSOR_MAP_INTERLEAVE_NONE, CU_TENSOR_MAP_SWIZZLE_128B,
        CU_TENSOR_MAP_L2_PROMOTION_L2_128B, CU_TENSOR_MAP_FLOAT_OOB_FILL_NONE);
}

extern "C" void kernel_launch(void* const* d_in, const int* in_sizes, int n_in,
                              void* d_out, int out_size) {
    (void)in_sizes; (void)n_in; (void)out_size;

    const void*  X_raw  = d_in[0];
    const void*  Wg_raw = d_in[1];
    const void*  bg_raw = d_in[2];
    const void*  Wu_raw = d_in[3];
    const void*  bu_raw = d_in[4];
    const void*  Wd_raw = d_in[5];
    const float* ag  = (const float*)d_in[6];
    const float* bgs = (const float*)d_in[7];
    const float* au  = (const float*)d_in[8];
    const float* bus = (const float*)d_in[9];
    const float* ad  = (const float*)d_in[10];
    const float* bd  = (const float*)d_in[11];
    float* out = (float*)d_out;

    void *ppool = nullptr, *pbg = nullptr, *pbu = nullptr, *pprod = nullptr;
    cudaGetSymbolAddress(&ppool, g_pool);
    cudaGetSymbolAddress(&pbg,   g_bg8);
    cudaGetSymbolAddress(&pbu,   g_bu8);
    cudaGetSymbolAddress(&pprod, g_prod8);

    PFN_encodeTiled enc = get_encoder();
    if (!enc || !ppool || !pprod) return;

    int8_t* pX  = (int8_t*)ppool + POOL_X_OFF;
    int8_t* pWg = (int8_t*)ppool + POOL_WG_OFF;
    int8_t* pWu = (int8_t*)ppool + POOL_WU_OFF;
    int8_t* pWd = (int8_t*)ppool + POOL_WD_OFF;   // reused after kernel 1

    // 1) probe wire dtype (int8 vs int32-promoted)
    probe_kernel<<<1, 32>>>(Wg_raw);

    // 2) pack phase-1 operands
    const int nX  = M_TOK * H_DIM / 16;      // 1048576
    const int nW  = F_DIM * H_DIM / 16;      // 2818048
    const int nB  = F_DIM / 16;              // 688
    pack_kernel<<<(nX + 255) / 256, 256>>>(pX,  X_raw,  nX);
    pack_kernel<<<(nW + 255) / 256, 256>>>(pWg, Wg_raw, nW);
    pack_kernel<<<(nW + 255) / 256, 256>>>(pWu, Wu_raw, nW);
    pack_kernel<<<(nB + 255) / 256, 256>>>((int8_t*)pbg, bg_raw, nB);
    pack_kernel<<<(nB + 255) / 256, 256>>>((int8_t*)pbu, bu_raw, nB);

    // 3) descriptors
    CUtensorMap tmX, tmWg, tmWu, tmP, tmWd;
    make2d(enc, &tmX,  pX,    H_DIM, M_TOK, H_DIM, 128, 128);
    make2d(enc, &tmWg, pWg,   H_DIM, F_DIM, H_DIM, 128, 128);
    make2d(enc, &tmWu, pWu,   H_DIM, F_DIM, H_DIM, 128, 128);
    make2d(enc, &tmP,  pprod, F_DIM, M_TOK, F_DIM, 128, 256);
    make2d(enc, &tmWd, pWd,   F_DIM, H_DIM, F_DIM, 128, 128);

    cudaFuncSetAttribute(mlp_gateup_kernel,
                         cudaFuncAttributeMaxDynamicSharedMemorySize, K1_SMEM);
    cudaFuncSetAttribute(mlp_down_kernel,
                         cudaFuncAttributeMaxDynamicSharedMemorySize, K2_SMEM);

    // 4) kernel 1 (consumes X/Wg/Wu from pool)
    dim3 g1(M_TOK / 128, F_DIM / 128);   // (32, 86)
    mlp_gateup_kernel<<<g1, 256, K1_SMEM>>>(tmX, tmWg, tmWu,
                                            (const int8_t*)pbg, (const int8_t*)pbu,
                                            ag, bgs, au, bus);

    // 5) pack Wd into the pool (X/Wg now dead; stream order guarantees safety)
    pack_kernel<<<(nW + 255) / 256, 256>>>(pWd, Wd_raw, nW);

    // 6) kernel 2
    dim3 g2(M_TOK / 256, H_DIM / 128);   // (16, 32)
    mlp_down_kernel<<<g2, 256, K2_SMEM>>>(tmP, tmWd, ad, bd, out);
}